// round 10
// baseline (speedup 1.0000x reference)
#include <cuda_runtime.h>
#include <cuda_fp16.h>
#include <mma.h>
#include <cstdint>

using namespace nvcuda;

#define N_NODES_MAX 100032
#define FDIM 256
#define ROW_CAP 128          // max degree capacity (Poisson(32); max ~59 expected)

// ---- device scratch (static .bss, no runtime alloc) ----
__device__ __half g_support_h[(size_t)N_NODES_MAX * FDIM];       // X @ W in fp16 (51 MB)
__device__ int    g_cursor[N_NODES_MAX];                         // zero-init; gather re-zeros
__device__ int2   g_pedge[(size_t)N_NODES_MAX * ROW_CAP];        // padded {col,val} buckets (102 MB)

// ---------------------------------------------------------------------------
// fp16 WMMA GEMM: support[M,256] = A[M,256] @ B[256,256], fp32 accum, fp16 out.
// BM=128 BN=128 BK=64, 256 threads (8 warps: 4m x 2n), warp tile 32x64.
// Single-buffered smem; epilogue staging aliases the A-tile region.
// ---------------------------------------------------------------------------
#define AS_BYTES (128 * 72 * 2)   // 18432
#define BS_BYTES (64 * 136 * 2)   // 17408

__global__ __launch_bounds__(256) void gemm_fp16_kernel(const float* __restrict__ A,
                                                        const float* __restrict__ B,
                                                        int M) {
    __shared__ char smem_raw[AS_BYTES + BS_BYTES];
    __half (*As)[72]  = reinterpret_cast<__half(*)[72]>(smem_raw);
    __half (*Bs)[136] = reinterpret_cast<__half(*)[136]>(smem_raw + AS_BYTES);

    const int tid = threadIdx.x;
    const int wid = tid >> 5;
    const int lane = tid & 31;
    const int warp_m = wid & 3;
    const int warp_n = wid >> 2;
    const int block_m = blockIdx.x * 128;
    const int block_n = blockIdx.y * 128;

    wmma::fragment<wmma::accumulator, 16, 16, 16, float> c[2][4];
#pragma unroll
    for (int i = 0; i < 2; i++)
#pragma unroll
        for (int j = 0; j < 4; j++) wmma::fill_fragment(c[i][j], 0.0f);

    for (int k0 = 0; k0 < FDIM; k0 += 64) {
        __syncthreads();
        // A tile: 128 rows x 64 k fp32 = 2048 float4; 8 per thread
#pragma unroll
        for (int i = 0; i < 8; i++) {
            int f = tid + i * 256;
            int row = f >> 4;             // 0..127
            int col4 = (f & 15) * 4;      // 0..60
            int grow = block_m + row;
            float4 v = make_float4(0.f, 0.f, 0.f, 0.f);
            if (grow < M)
                v = *reinterpret_cast<const float4*>(A + (size_t)grow * FDIM + k0 + col4);
            __half2 h0 = __floats2half2_rn(v.x, v.y);
            __half2 h1 = __floats2half2_rn(v.z, v.w);
            uint2 pack;
            pack.x = *reinterpret_cast<uint32_t*>(&h0);
            pack.y = *reinterpret_cast<uint32_t*>(&h1);
            *reinterpret_cast<uint2*>(&As[row][col4]) = pack;
        }
        // B tile: 64 k x 128 n fp32 = 2048 float4; 8 per thread
#pragma unroll
        for (int i = 0; i < 8; i++) {
            int f = tid + i * 256;
            int row = f >> 5;             // 0..63
            int col4 = (f & 31) * 4;      // 0..124
            float4 v = *reinterpret_cast<const float4*>(B + (size_t)(k0 + row) * FDIM + block_n + col4);
            __half2 h0 = __floats2half2_rn(v.x, v.y);
            __half2 h1 = __floats2half2_rn(v.z, v.w);
            uint2 pack;
            pack.x = *reinterpret_cast<uint32_t*>(&h0);
            pack.y = *reinterpret_cast<uint32_t*>(&h1);
            *reinterpret_cast<uint2*>(&Bs[row][col4]) = pack;
        }
        __syncthreads();

#pragma unroll
        for (int ks = 0; ks < 4; ks++) {
            wmma::fragment<wmma::matrix_a, 16, 16, 16, __half, wmma::row_major> a[2];
            wmma::fragment<wmma::matrix_b, 16, 16, 16, __half, wmma::row_major> b[4];
#pragma unroll
            for (int i = 0; i < 2; i++)
                wmma::load_matrix_sync(a[i], &As[warp_m * 32 + i * 16][ks * 16], 72);
#pragma unroll
            for (int j = 0; j < 4; j++)
                wmma::load_matrix_sync(b[j], &Bs[ks * 16][warp_n * 64 + j * 16], 136);
#pragma unroll
            for (int i = 0; i < 2; i++)
#pragma unroll
                for (int j = 0; j < 4; j++)
                    wmma::mma_sync(c[i][j], a[i], b[j], c[i][j]);
        }
    }

    // Epilogue: stage fragments in smem (aliases As region — dead now).
    __syncthreads();
    float (*Cstage)[16][20] = reinterpret_cast<float(*)[16][20]>(smem_raw);
#pragma unroll
    for (int i = 0; i < 2; i++) {
#pragma unroll
        for (int j = 0; j < 4; j++) {
            __syncwarp();
            wmma::store_matrix_sync(&Cstage[wid][0][0], c[i][j], 20, wmma::mem_row_major);
            __syncwarp();
            int r = lane >> 1;
            int half8 = (lane & 1) * 8;
            int grow = block_m + warp_m * 32 + i * 16 + r;
            int gcol = block_n + warp_n * 64 + j * 16 + half8;
            if (grow < M) {
                const float* src = &Cstage[wid][r][half8];
                __half2 h0 = __floats2half2_rn(src[0], src[1]);
                __half2 h1 = __floats2half2_rn(src[2], src[3]);
                __half2 h2 = __floats2half2_rn(src[4], src[5]);
                __half2 h3 = __floats2half2_rn(src[6], src[7]);
                uint4 pack;
                pack.x = *reinterpret_cast<uint32_t*>(&h0);
                pack.y = *reinterpret_cast<uint32_t*>(&h1);
                pack.z = *reinterpret_cast<uint32_t*>(&h2);
                pack.w = *reinterpret_cast<uint32_t*>(&h3);
                *reinterpret_cast<uint4*>(g_support_h + (size_t)grow * FDIM + gcol) = pack;
            }
        }
    }
}

// ---------------------------------------------------------------------------
// Direct padded bucketing: pedge[r*ROW_CAP + pos] = {col, val}; cursor = degree.
// ---------------------------------------------------------------------------
__global__ __launch_bounds__(256) void bucket_kernel(const int* __restrict__ rows,
                                                     const int* __restrict__ cols,
                                                     const float* __restrict__ vals, int E) {
    const int tid = blockIdx.x * 256 + threadIdx.x;
    const int e4 = E >> 2;
    if (tid < e4) {
        int4 r = __ldg(&reinterpret_cast<const int4*>(rows)[tid]);
        int4 c = __ldg(&reinterpret_cast<const int4*>(cols)[tid]);
        float4 v = __ldg(&reinterpret_cast<const float4*>(vals)[tid]);
        int p0 = atomicAdd(&g_cursor[r.x], 1);
        int p1 = atomicAdd(&g_cursor[r.y], 1);
        int p2 = atomicAdd(&g_cursor[r.z], 1);
        int p3 = atomicAdd(&g_cursor[r.w], 1);
        g_pedge[(size_t)r.x * ROW_CAP + p0] = make_int2(c.x, __float_as_int(v.x));
        g_pedge[(size_t)r.y * ROW_CAP + p1] = make_int2(c.y, __float_as_int(v.y));
        g_pedge[(size_t)r.z * ROW_CAP + p2] = make_int2(c.z, __float_as_int(v.z));
        g_pedge[(size_t)r.w * ROW_CAP + p3] = make_int2(c.w, __float_as_int(v.w));
    }
    int t = (e4 << 2) + tid;
    if (t >= (e4 << 2) && t < E && tid < 4) {
        int r = __ldg(&rows[t]);
        int pos = atomicAdd(&g_cursor[r], 1);
        g_pedge[(size_t)r * ROW_CAP + pos] = make_int2(__ldg(&cols[t]), __float_as_int(__ldg(&vals[t])));
    }
}

// ---------------------------------------------------------------------------
// Pull-mode SpMM: one warp per row; lane owns 8 halfs (16B load).
// Reads degree from g_cursor[r] and resets it to 0 for the next replay.
// ---------------------------------------------------------------------------
__global__ __launch_bounds__(256) void gather_kernel(const float* __restrict__ bias,
                                                     float* __restrict__ out, int M) {
    const int warp = (blockIdx.x * 256 + threadIdx.x) >> 5;
    const int lane = threadIdx.x & 31;
    if (warp >= M) return;
    const int r = warp;

    const int deg = g_cursor[r];

    const float4* bias4 = reinterpret_cast<const float4*>(bias);
    float4 a0 = bias4[lane * 2];
    float4 a1 = bias4[lane * 2 + 1];

    const uint4* sup = reinterpret_cast<const uint4*>(g_support_h);
    const int2* edges = g_pedge + (size_t)r * ROW_CAP;

    int2 nxt = (deg > 0) ? __ldg(&edges[0]) : make_int2(0, 0);
    for (int j = 0; j < deg; j++) {
        const int2 cur = nxt;
        if (j + 1 < deg) nxt = __ldg(&edges[j + 1]);
        const float v = __int_as_float(cur.y);
        uint4 h = __ldg(&sup[(size_t)cur.x * 32 + lane]);

        float2 f0 = __half22float2(*reinterpret_cast<__half2*>(&h.x));
        float2 f1 = __half22float2(*reinterpret_cast<__half2*>(&h.y));
        float2 f2 = __half22float2(*reinterpret_cast<__half2*>(&h.z));
        float2 f3 = __half22float2(*reinterpret_cast<__half2*>(&h.w));

        a0.x = fmaf(v, f0.x, a0.x);
        a0.y = fmaf(v, f0.y, a0.y);
        a0.z = fmaf(v, f1.x, a0.z);
        a0.w = fmaf(v, f1.y, a0.w);
        a1.x = fmaf(v, f2.x, a1.x);
        a1.y = fmaf(v, f2.y, a1.y);
        a1.z = fmaf(v, f3.x, a1.z);
        a1.w = fmaf(v, f3.y, a1.w);
    }

    if (lane == 0) g_cursor[r] = 0;  // restore zero invariant for next graph replay

    float4* out4 = reinterpret_cast<float4*>(out);
    out4[(size_t)r * 64 + lane * 2] = a0;
    out4[(size_t)r * 64 + lane * 2 + 1] = a1;
}

extern "C" void kernel_launch(void* const* d_in, const int* in_sizes, int n_in,
                              void* d_out, int out_size) {
    const float* input  = (const float*)d_in[0];
    const float* weight = (const float*)d_in[1];
    const float* bias   = (const float*)d_in[2];
    const int*   e_rows = (const int*)d_in[3];
    const int*   e_cols = (const int*)d_in[4];
    const float* e_vals = (const float*)d_in[5];
    float* out = (float*)d_out;

    const int M = in_sizes[0] / FDIM;
    const int E = in_sizes[3];
    const int e4 = E >> 2;
    const int eblocks = (e4 + 255) / 256;

    // 1) support = X @ W  (fp16 tensor cores)
    dim3 ggrid((M + 127) / 128, FDIM / 128);
    gemm_fp16_kernel<<<ggrid, 256>>>(input, weight, M);

    // 2) direct padded bucketing
    bucket_kernel<<<eblocks, 256>>>(e_rows, e_cols, e_vals, E);

    // 3) pull-mode SpMM + bias (also resets cursors)
    gather_kernel<<<(M * 32 + 255) / 256, 256>>>(bias, out, M);
}

// round 11
// speedup vs baseline: 1.0247x; 1.0247x over previous
#include <cuda_runtime.h>
#include <cuda_fp16.h>
#include <mma.h>
#include <cstdint>

using namespace nvcuda;

#define N_NODES_MAX 100032
#define FDIM 256
#define ROW_CAP 128          // max degree capacity (Poisson(32); max ~59 expected)

// ---- device scratch (static .bss, no runtime alloc) ----
__device__ __half g_support_h[(size_t)N_NODES_MAX * FDIM];       // X @ W in fp16 (51 MB)
__device__ int    g_cursor[N_NODES_MAX];                         // zero-init; gather re-zeros
__device__ int2   g_pedge[(size_t)N_NODES_MAX * ROW_CAP];        // padded {col,val} buckets (102 MB)

// ---------------------------------------------------------------------------
// fp16 WMMA GEMM (R9 version — best measured): BM=128 BN=128 BK=32,
// 256 threads (8 warps: 4m x 2n), warp tile 32x64, double-buffered smem.
// ---------------------------------------------------------------------------
__global__ __launch_bounds__(256) void gemm_fp16_kernel(const float* __restrict__ A,
                                                        const float* __restrict__ B,
                                                        int M) {
    __shared__ __half As[2][128][40];
    __shared__ __half Bs[2][32][136];
    __shared__ float  Cstage[8][16][20];

    const int tid = threadIdx.x;
    const int wid = tid >> 5;
    const int lane = tid & 31;
    const int warp_m = wid & 3;
    const int warp_n = wid >> 2;
    const int block_m = blockIdx.x * 128;
    const int block_n = blockIdx.y * 128;

    wmma::fragment<wmma::accumulator, 16, 16, 16, float> c[2][4];
#pragma unroll
    for (int i = 0; i < 2; i++)
#pragma unroll
        for (int j = 0; j < 4; j++) wmma::fill_fragment(c[i][j], 0.0f);

    float4 va[4], vb[4];

    auto load_tiles = [&](int k0) {
#pragma unroll
        for (int i = 0; i < 4; i++) {
            int f = tid + i * 256;
            int row = f >> 3;
            int col4 = (f & 7) * 4;
            int grow = block_m + row;
            va[i] = make_float4(0.f, 0.f, 0.f, 0.f);
            if (grow < M)
                va[i] = *reinterpret_cast<const float4*>(A + (size_t)grow * FDIM + k0 + col4);
        }
#pragma unroll
        for (int i = 0; i < 4; i++) {
            int f = tid + i * 256;
            int row = f >> 5;
            int col4 = (f & 31) * 4;
            vb[i] = *reinterpret_cast<const float4*>(B + (size_t)(k0 + row) * FDIM + block_n + col4);
        }
    };

    auto store_tiles = [&](int b) {
#pragma unroll
        for (int i = 0; i < 4; i++) {
            int f = tid + i * 256;
            int row = f >> 3;
            int col4 = (f & 7) * 4;
            __half2 h0 = __floats2half2_rn(va[i].x, va[i].y);
            __half2 h1 = __floats2half2_rn(va[i].z, va[i].w);
            uint2 pack;
            pack.x = *reinterpret_cast<uint32_t*>(&h0);
            pack.y = *reinterpret_cast<uint32_t*>(&h1);
            *reinterpret_cast<uint2*>(&As[b][row][col4]) = pack;
        }
#pragma unroll
        for (int i = 0; i < 4; i++) {
            int f = tid + i * 256;
            int row = f >> 5;
            int col4 = (f & 31) * 4;
            __half2 h0 = __floats2half2_rn(vb[i].x, vb[i].y);
            __half2 h1 = __floats2half2_rn(vb[i].z, vb[i].w);
            uint2 pack;
            pack.x = *reinterpret_cast<uint32_t*>(&h0);
            pack.y = *reinterpret_cast<uint32_t*>(&h1);
            *reinterpret_cast<uint2*>(&Bs[b][row][col4]) = pack;
        }
    };

    load_tiles(0);
    store_tiles(0);
    __syncthreads();

    int buf = 0;
    for (int k0 = 0; k0 < FDIM; k0 += 32) {
        const bool has_next = (k0 + 32 < FDIM);
        if (has_next) load_tiles(k0 + 32);

#pragma unroll
        for (int ks = 0; ks < 2; ks++) {
            wmma::fragment<wmma::matrix_a, 16, 16, 16, __half, wmma::row_major> a[2];
            wmma::fragment<wmma::matrix_b, 16, 16, 16, __half, wmma::row_major> b[4];
#pragma unroll
            for (int i = 0; i < 2; i++)
                wmma::load_matrix_sync(a[i], &As[buf][warp_m * 32 + i * 16][ks * 16], 40);
#pragma unroll
            for (int j = 0; j < 4; j++)
                wmma::load_matrix_sync(b[j], &Bs[buf][ks * 16][warp_n * 64 + j * 16], 136);
#pragma unroll
            for (int i = 0; i < 2; i++)
#pragma unroll
                for (int j = 0; j < 4; j++)
                    wmma::mma_sync(c[i][j], a[i], b[j], c[i][j]);
        }

        if (has_next) {
            store_tiles(buf ^ 1);
            __syncthreads();
            buf ^= 1;
        }
    }

#pragma unroll
    for (int i = 0; i < 2; i++) {
#pragma unroll
        for (int j = 0; j < 4; j++) {
            __syncwarp();
            wmma::store_matrix_sync(&Cstage[wid][0][0], c[i][j], 20, wmma::mem_row_major);
            __syncwarp();
            int r = lane >> 1;
            int half8 = (lane & 1) * 8;
            int grow = block_m + warp_m * 32 + i * 16 + r;
            int gcol = block_n + warp_n * 64 + j * 16 + half8;
            if (grow < M) {
                const float* src = &Cstage[wid][r][half8];
                __half2 h0 = __floats2half2_rn(src[0], src[1]);
                __half2 h1 = __floats2half2_rn(src[2], src[3]);
                __half2 h2 = __floats2half2_rn(src[4], src[5]);
                __half2 h3 = __floats2half2_rn(src[6], src[7]);
                uint4 pack;
                pack.x = *reinterpret_cast<uint32_t*>(&h0);
                pack.y = *reinterpret_cast<uint32_t*>(&h1);
                pack.z = *reinterpret_cast<uint32_t*>(&h2);
                pack.w = *reinterpret_cast<uint32_t*>(&h3);
                *reinterpret_cast<uint4*>(g_support_h + (size_t)grow * FDIM + gcol) = pack;
            }
        }
    }
}

// ---------------------------------------------------------------------------
// Direct padded bucketing: pedge[r*ROW_CAP + pos] = {col, val}; cursor = degree.
// ---------------------------------------------------------------------------
__global__ __launch_bounds__(256) void bucket_kernel(const int* __restrict__ rows,
                                                     const int* __restrict__ cols,
                                                     const float* __restrict__ vals, int E) {
    const int tid = blockIdx.x * 256 + threadIdx.x;
    const int e4 = E >> 2;
    if (tid < e4) {
        int4 r = __ldg(&reinterpret_cast<const int4*>(rows)[tid]);
        int4 c = __ldg(&reinterpret_cast<const int4*>(cols)[tid]);
        float4 v = __ldg(&reinterpret_cast<const float4*>(vals)[tid]);
        int p0 = atomicAdd(&g_cursor[r.x], 1);
        int p1 = atomicAdd(&g_cursor[r.y], 1);
        int p2 = atomicAdd(&g_cursor[r.z], 1);
        int p3 = atomicAdd(&g_cursor[r.w], 1);
        g_pedge[(size_t)r.x * ROW_CAP + p0] = make_int2(c.x, __float_as_int(v.x));
        g_pedge[(size_t)r.y * ROW_CAP + p1] = make_int2(c.y, __float_as_int(v.y));
        g_pedge[(size_t)r.z * ROW_CAP + p2] = make_int2(c.z, __float_as_int(v.z));
        g_pedge[(size_t)r.w * ROW_CAP + p3] = make_int2(c.w, __float_as_int(v.w));
    }
    int t = (e4 << 2) + tid;
    if (t >= (e4 << 2) && t < E && tid < 4) {
        int r = __ldg(&rows[t]);
        int pos = atomicAdd(&g_cursor[r], 1);
        g_pedge[(size_t)r * ROW_CAP + pos] = make_int2(__ldg(&cols[t]), __float_as_int(__ldg(&vals[t])));
    }
}

// ---------------------------------------------------------------------------
// Pull-mode SpMM: one warp per row; lane owns 8 halfs (16B load).
// ---------------------------------------------------------------------------
__global__ __launch_bounds__(256) void gather_kernel(const float* __restrict__ bias,
                                                     float* __restrict__ out, int M) {
    const int warp = (blockIdx.x * 256 + threadIdx.x) >> 5;
    const int lane = threadIdx.x & 31;
    if (warp >= M) return;
    const int r = warp;

    const int deg = g_cursor[r];

    const float4* bias4 = reinterpret_cast<const float4*>(bias);
    float4 a0 = bias4[lane * 2];
    float4 a1 = bias4[lane * 2 + 1];

    const uint4* sup = reinterpret_cast<const uint4*>(g_support_h);
    const int2* edges = g_pedge + (size_t)r * ROW_CAP;

    int2 nxt = (deg > 0) ? __ldg(&edges[0]) : make_int2(0, 0);
    for (int j = 0; j < deg; j++) {
        const int2 cur = nxt;
        if (j + 1 < deg) nxt = __ldg(&edges[j + 1]);
        const float v = __int_as_float(cur.y);
        uint4 h = __ldg(&sup[(size_t)cur.x * 32 + lane]);

        float2 f0 = __half22float2(*reinterpret_cast<__half2*>(&h.x));
        float2 f1 = __half22float2(*reinterpret_cast<__half2*>(&h.y));
        float2 f2 = __half22float2(*reinterpret_cast<__half2*>(&h.z));
        float2 f3 = __half22float2(*reinterpret_cast<__half2*>(&h.w));

        a0.x = fmaf(v, f0.x, a0.x);
        a0.y = fmaf(v, f0.y, a0.y);
        a0.z = fmaf(v, f1.x, a0.z);
        a0.w = fmaf(v, f1.y, a0.w);
        a1.x = fmaf(v, f2.x, a1.x);
        a1.y = fmaf(v, f2.y, a1.y);
        a1.z = fmaf(v, f3.x, a1.z);
        a1.w = fmaf(v, f3.y, a1.w);
    }

    if (lane == 0) g_cursor[r] = 0;  // restore zero invariant for next graph replay

    float4* out4 = reinterpret_cast<float4*>(out);
    out4[(size_t)r * 64 + lane * 2] = a0;
    out4[(size_t)r * 64 + lane * 2 + 1] = a1;
}

extern "C" void kernel_launch(void* const* d_in, const int* in_sizes, int n_in,
                              void* d_out, int out_size) {
    const float* input  = (const float*)d_in[0];
    const float* weight = (const float*)d_in[1];
    const float* bias   = (const float*)d_in[2];
    const int*   e_rows = (const int*)d_in[3];
    const int*   e_cols = (const int*)d_in[4];
    const float* e_vals = (const float*)d_in[5];
    float* out = (float*)d_out;

    const int M = in_sizes[0] / FDIM;
    const int E = in_sizes[3];
    const int e4 = E >> 2;
    const int eblocks = (e4 + 255) / 256;

    // Lazily-created side stream + events (host objects only; created on the
    // first, uncaptured correctness call; identical launch pattern every call).
    static cudaStream_t s_side = nullptr;
    static cudaEvent_t  ev_fork = nullptr, ev_join = nullptr;
    if (s_side == nullptr) {
        cudaStreamCreateWithFlags(&s_side, cudaStreamNonBlocking);
        cudaEventCreateWithFlags(&ev_fork, cudaEventDisableTiming);
        cudaEventCreateWithFlags(&ev_join, cudaEventDisableTiming);
    }

    // Fork: bucket runs concurrently with GEMM (independent data).
    cudaEventRecord(ev_fork, 0);
    cudaStreamWaitEvent(s_side, ev_fork, 0);

    bucket_kernel<<<eblocks, 256, 0, s_side>>>(e_rows, e_cols, e_vals, E);
    cudaEventRecord(ev_join, s_side);

    dim3 ggrid((M + 127) / 128, FDIM / 128);
    gemm_fp16_kernel<<<ggrid, 256>>>(input, weight, M);

    // Join: gather needs both GEMM (support) and bucket (edges).
    cudaStreamWaitEvent(0, ev_join, 0);

    gather_kernel<<<(M * 32 + 255) / 256, 256>>>(bias, out, M);
}